// round 1
// baseline (speedup 1.0000x reference)
#include <cuda_runtime.h>
#include <math.h>

// ----------------------------------------------------------------------------
// Shapes (fixed for this problem)
// ----------------------------------------------------------------------------
#define B_   4
#define L_   1024
#define D_   1024
#define H_   16
#define HD_  64
#define FF_  4096
#define NS_  64
#define M_   (B_ * L_)          // 4096 rows

// Scratch layout (floats)
#define OFF_LN    0ull                               // 4096*1024
#define OFF_QKV   (OFF_LN   + 4194304ull)            // 4096*3072
#define OFF_ATTN  (OFF_QKV  + 12582912ull)           // 4096*1024
#define OFF_X1    (OFF_ATTN + 4194304ull)            // 4096*1024
#define OFF_X2    (OFF_X1   + 4194304ull)            // 4096*1024
#define OFF_KVN   (OFF_X2   + 4194304ull)            // 256*1024
#define OFF_CKV   (OFF_KVN  + 262144ull)             // 256*2048
#define OFF_F     (OFF_CKV  + 524288ull)             // 4096*8192
#define OFF_GG    (OFF_F    + 33554432ull)           // 4096*4096
#define SCRATCH_FLOATS (OFF_GG + 16777216ull)        // 80,478,208 floats

__device__ float g_scratch[SCRATCH_FLOATS];

// ----------------------------------------------------------------------------
// LayerNorm: one block per row, 256 threads, D=1024 (one float4 per thread)
// ----------------------------------------------------------------------------
__global__ __launch_bounds__(256)
void ln_kernel(const float* __restrict__ x, const float* __restrict__ g,
               const float* __restrict__ b, float* __restrict__ y) {
    const int row = blockIdx.x;
    const int t = threadIdx.x;
    const float4 v = ((const float4*)(x + (size_t)row * D_))[t];

    __shared__ float red[8];
    __shared__ float stat[2];

    float s = v.x + v.y + v.z + v.w;
    #pragma unroll
    for (int o = 16; o; o >>= 1) s += __shfl_xor_sync(0xffffffffu, s, o);
    if ((t & 31) == 0) red[t >> 5] = s;
    __syncthreads();
    if (t == 0) {
        float s2 = 0.f;
        #pragma unroll
        for (int i = 0; i < 8; i++) s2 += red[i];
        stat[0] = s2 * (1.0f / D_);
    }
    __syncthreads();
    const float mu = stat[0];
    const float dx = v.x - mu, dy = v.y - mu, dz = v.z - mu, dw = v.w - mu;

    float q = dx * dx + dy * dy + dz * dz + dw * dw;
    #pragma unroll
    for (int o = 16; o; o >>= 1) q += __shfl_xor_sync(0xffffffffu, q, o);
    if ((t & 31) == 0) red[t >> 5] = q;
    __syncthreads();
    if (t == 0) {
        float s2 = 0.f;
        #pragma unroll
        for (int i = 0; i < 8; i++) s2 += red[i];
        stat[1] = rsqrtf(s2 * (1.0f / D_) + 1e-5f);
    }
    __syncthreads();
    const float rs = stat[1];

    const float4 gv = ((const float4*)g)[t];
    const float4 bv = ((const float4*)b)[t];
    float4 out;
    out.x = dx * rs * gv.x + bv.x;
    out.y = dy * rs * gv.y + bv.y;
    out.z = dz * rs * gv.z + bv.z;
    out.w = dw * rs * gv.w + bv.w;
    ((float4*)(y + (size_t)row * D_))[t] = out;
}

// ----------------------------------------------------------------------------
// SGEMM: C[M,N] = A[M,K] @ W[N,K]^T + bias, with epilogue variants.
// 128x128 block tile, K-step 8, 256 threads, 8x8 microtile.
// EPI: 0 = bias only, 1 = bias + residual, 2 = sigmoid(gate)*(..)+residual
// M,N multiples of 128; K multiple of 8.
// ----------------------------------------------------------------------------
template <int EPI>
__global__ __launch_bounds__(256)
void gemm_kernel(const float* __restrict__ A, const float* __restrict__ W,
                 const float* __restrict__ bias, const float* __restrict__ res,
                 const float* __restrict__ gatep, float* __restrict__ C,
                 int M, int N, int K) {
    __shared__ float As[8][128];
    __shared__ float Bs[8][128];

    const int t = threadIdx.x;
    const int tx = t & 15;         // 0..15 -> n microtile
    const int ty = t >> 4;         // 0..15 -> m microtile
    const int mBase = blockIdx.y * 128;
    const int nBase = blockIdx.x * 128;

    const int lrow = t >> 1;       // 0..127
    const int lk = (t & 1) * 4;    // 0 or 4
    const float* Ap = A + (size_t)(mBase + lrow) * K + lk;
    const float* Wp = W + (size_t)(nBase + lrow) * K + lk;

    float acc[8][8];
    #pragma unroll
    for (int i = 0; i < 8; i++)
        #pragma unroll
        for (int j = 0; j < 8; j++) acc[i][j] = 0.f;

    for (int k0 = 0; k0 < K; k0 += 8) {
        const float4 a = *(const float4*)(Ap + k0);
        const float4 w = *(const float4*)(Wp + k0);
        As[lk + 0][lrow] = a.x; As[lk + 1][lrow] = a.y;
        As[lk + 2][lrow] = a.z; As[lk + 3][lrow] = a.w;
        Bs[lk + 0][lrow] = w.x; Bs[lk + 1][lrow] = w.y;
        Bs[lk + 2][lrow] = w.z; Bs[lk + 3][lrow] = w.w;
        __syncthreads();

        #pragma unroll
        for (int kk = 0; kk < 8; kk++) {
            const float4 a0 = *(const float4*)&As[kk][ty * 8];
            const float4 a1 = *(const float4*)&As[kk][ty * 8 + 4];
            const float4 b0 = *(const float4*)&Bs[kk][tx * 8];
            const float4 b1 = *(const float4*)&Bs[kk][tx * 8 + 4];
            const float ar[8] = {a0.x, a0.y, a0.z, a0.w, a1.x, a1.y, a1.z, a1.w};
            const float br[8] = {b0.x, b0.y, b0.z, b0.w, b1.x, b1.y, b1.z, b1.w};
            #pragma unroll
            for (int i = 0; i < 8; i++)
                #pragma unroll
                for (int j = 0; j < 8; j++) acc[i][j] += ar[i] * br[j];
        }
        __syncthreads();
    }

    float gs = 1.f;
    if (EPI == 2) gs = 1.f / (1.f + __expf(-gatep[0]));

    #pragma unroll
    for (int i = 0; i < 8; i++) {
        const int m = mBase + ty * 8 + i;
        float* Crow = C + (size_t)m * N + nBase;
        const float* Rrow = (EPI >= 1) ? (res + (size_t)m * N + nBase) : nullptr;
        #pragma unroll
        for (int j = 0; j < 8; j++) {
            const int n = tx * 8 + j;
            float c = acc[i][j] + bias[nBase + n];
            if (EPI == 1) c += Rrow[n];
            if (EPI == 2) c = gs * c + Rrow[n];
            Crow[n] = c;
        }
    }
}

// ----------------------------------------------------------------------------
// Flash attention, fp32, HD=64, 64q x 64k tiles, 256 threads.
// Q rows at Qb + (b*Lq + q)*ldq + h*64 ; K/V similar with Lkv rows.
// bias (may be null): bias[(bh*Lq + q)*Lkv + k], added AFTER the 1/8 scale.
// Output Ob + (b*Lq + q)*ldo + h*64.
// grid: (Lq/64, B*H)
// ----------------------------------------------------------------------------
__global__ __launch_bounds__(256)
void flash_kernel(const float* __restrict__ Qb, int ldq,
                  const float* __restrict__ Kb, int ldk,
                  const float* __restrict__ Vb, int ldv,
                  const float* __restrict__ bias,
                  float* __restrict__ Ob, int ldo,
                  int Lq, int Lkv) {
    __shared__ float Qt[64][64];   // transposed: Qt[d][q]
    __shared__ float KP[64][64];   // K phase: KP[d][k] ; P phase: KP[k][q]
    __shared__ float Vs[64][64];   // natural:  Vs[k][d]

    const int bh = blockIdx.y;
    const int b = bh >> 4;          // H=16
    const int h = bh & 15;
    const int q0 = blockIdx.x * 64;
    const int t = threadIdx.x;
    const int tx = t & 15;          // column group
    const int ty = t >> 4;          // row group

    const int lrow = t >> 2;        // 0..63
    const int lc0 = (t & 3) * 16;   // 0,16,32,48

    // Load Q tile transposed
    {
        const float* qrow = Qb + (size_t)(b * Lq + q0 + lrow) * ldq + h * HD_ + lc0;
        #pragma unroll
        for (int c = 0; c < 16; c += 4) {
            const float4 v = *(const float4*)(qrow + c);
            Qt[lc0 + c + 0][lrow] = v.x; Qt[lc0 + c + 1][lrow] = v.y;
            Qt[lc0 + c + 2][lrow] = v.z; Qt[lc0 + c + 3][lrow] = v.w;
        }
    }

    float o[4][4];
    float m[4], l[4];
    #pragma unroll
    for (int i = 0; i < 4; i++) {
        m[i] = -1e30f; l[i] = 0.f;
        #pragma unroll
        for (int j = 0; j < 4; j++) o[i][j] = 0.f;
    }
    const float invs = 0.125f;  // 1/sqrt(64)

    for (int k0 = 0; k0 < Lkv; k0 += 64) {
        __syncthreads();  // previous PV / Q store fence
        {
            const float* krow = Kb + (size_t)(b * Lkv + k0 + lrow) * ldk + h * HD_ + lc0;
            const float* vrow = Vb + (size_t)(b * Lkv + k0 + lrow) * ldv + h * HD_ + lc0;
            #pragma unroll
            for (int c = 0; c < 16; c += 4) {
                const float4 kv = *(const float4*)(krow + c);
                KP[lc0 + c + 0][lrow] = kv.x; KP[lc0 + c + 1][lrow] = kv.y;
                KP[lc0 + c + 2][lrow] = kv.z; KP[lc0 + c + 3][lrow] = kv.w;
                *(float4*)&Vs[lrow][lc0 + c] = *(const float4*)(vrow + c);
            }
        }
        __syncthreads();

        // S = Q K^T
        float s[4][4];
        #pragma unroll
        for (int i = 0; i < 4; i++)
            #pragma unroll
            for (int j = 0; j < 4; j++) s[i][j] = 0.f;
        #pragma unroll
        for (int kk = 0; kk < 64; kk++) {
            const float4 qa = *(const float4*)&Qt[kk][ty * 4];
            const float4 kb = *(const float4*)&KP[kk][tx * 4];
            const float qr[4] = {qa.x, qa.y, qa.z, qa.w};
            const float kr[4] = {kb.x, kb.y, kb.z, kb.w};
            #pragma unroll
            for (int i = 0; i < 4; i++)
                #pragma unroll
                for (int j = 0; j < 4; j++) s[i][j] += qr[i] * kr[j];
        }

        // scale + bias
        if (bias) {
            #pragma unroll
            for (int i = 0; i < 4; i++) {
                const float4 bb = *(const float4*)(bias +
                    ((size_t)bh * Lq + (q0 + ty * 4 + i)) * Lkv + k0 + tx * 4);
                s[i][0] = s[i][0] * invs + bb.x;
                s[i][1] = s[i][1] * invs + bb.y;
                s[i][2] = s[i][2] * invs + bb.z;
                s[i][3] = s[i][3] * invs + bb.w;
            }
        } else {
            #pragma unroll
            for (int i = 0; i < 4; i++)
                #pragma unroll
                for (int j = 0; j < 4; j++) s[i][j] *= invs;
        }

        __syncthreads();  // done reading KP as K; about to overwrite with P

        // online softmax (per 4 rows; reduce across the 16 tx lanes)
        #pragma unroll
        for (int i = 0; i < 4; i++) {
            float rm = fmaxf(fmaxf(s[i][0], s[i][1]), fmaxf(s[i][2], s[i][3]));
            #pragma unroll
            for (int off = 8; off; off >>= 1)
                rm = fmaxf(rm, __shfl_xor_sync(0xffffffffu, rm, off));
            const float mn = fmaxf(m[i], rm);
            const float sc = __expf(m[i] - mn);
            s[i][0] = __expf(s[i][0] - mn);
            s[i][1] = __expf(s[i][1] - mn);
            s[i][2] = __expf(s[i][2] - mn);
            s[i][3] = __expf(s[i][3] - mn);
            float rs = s[i][0] + s[i][1] + s[i][2] + s[i][3];
            #pragma unroll
            for (int off = 8; off; off >>= 1)
                rs += __shfl_xor_sync(0xffffffffu, rs, off);
            l[i] = l[i] * sc + rs;
            m[i] = mn;
            #pragma unroll
            for (int j = 0; j < 4; j++) o[i][j] *= sc;
        }

        // store P transposed: KP[k][q]
        #pragma unroll
        for (int j = 0; j < 4; j++) {
            const float4 pv = make_float4(s[0][j], s[1][j], s[2][j], s[3][j]);
            *(float4*)&KP[tx * 4 + j][ty * 4] = pv;
        }
        __syncthreads();

        // O += P V
        #pragma unroll
        for (int kk = 0; kk < 64; kk++) {
            const float4 pa = *(const float4*)&KP[kk][ty * 4];
            const float4 vb = *(const float4*)&Vs[kk][tx * 4];
            const float pr[4] = {pa.x, pa.y, pa.z, pa.w};
            const float vr[4] = {vb.x, vb.y, vb.z, vb.w};
            #pragma unroll
            for (int i = 0; i < 4; i++)
                #pragma unroll
                for (int j = 0; j < 4; j++) o[i][j] += pr[i] * vr[j];
        }
    }

    // normalize + store
    #pragma unroll
    for (int i = 0; i < 4; i++) {
        const float inv = 1.f / l[i];
        const float4 ov = make_float4(o[i][0] * inv, o[i][1] * inv,
                                      o[i][2] * inv, o[i][3] * inv);
        *(float4*)(Ob + (size_t)(b * Lq + q0 + ty * 4 + i) * ldo + h * HD_ + tx * 4) = ov;
    }
}

// ----------------------------------------------------------------------------
// GEGLU: gg[m][j] = f[m][j] * gelu_exact(f[m][FF+j]),  m<4096, j<4096
// Vectorized float4: one thread handles one float4 of the FF columns.
// ----------------------------------------------------------------------------
__device__ __forceinline__ float gelu_exact(float x) {
    return 0.5f * x * (1.0f + erff(x * 0.7071067811865476f));
}

__global__ __launch_bounds__(256)
void geglu_kernel(const float* __restrict__ f, float* __restrict__ gg) {
    const int idx4 = blockIdx.x * blockDim.x + threadIdx.x;  // 0 .. 4096*1024-1
    const int mrow = idx4 >> 10;
    const int j4 = (idx4 & 1023) * 4;
    const float4 val = *(const float4*)(f + (size_t)mrow * (2 * FF_) + j4);
    const float4 gt  = *(const float4*)(f + (size_t)mrow * (2 * FF_) + FF_ + j4);
    float4 out;
    out.x = val.x * gelu_exact(gt.x);
    out.y = val.y * gelu_exact(gt.y);
    out.z = val.z * gelu_exact(gt.z);
    out.w = val.w * gelu_exact(gt.w);
    *(float4*)(gg + (size_t)mrow * FF_ + j4) = out;
}

// ----------------------------------------------------------------------------
// Host orchestration
// ----------------------------------------------------------------------------
extern "C" void kernel_launch(void* const* d_in, const int* in_sizes, int n_in,
                              void* d_out, int out_size) {
    const float* x          = (const float*)d_in[0];
    const float* alibi      = (const float*)d_in[1];
    const float* species    = (const float*)d_in[2];
    const float* norm1_g    = (const float*)d_in[3];
    const float* norm1_b    = (const float*)d_in[4];
    const float* sa_wqkv    = (const float*)d_in[5];
    const float* sa_bqkv    = (const float*)d_in[6];
    const float* sa_wo      = (const float*)d_in[7];
    const float* sa_bo      = (const float*)d_in[8];
    const float* ca_nq_g    = (const float*)d_in[9];
    const float* ca_nq_b    = (const float*)d_in[10];
    const float* ca_nkv_g   = (const float*)d_in[11];
    const float* ca_nkv_b   = (const float*)d_in[12];
    const float* ca_wqkv    = (const float*)d_in[13];
    const float* ca_bqkv    = (const float*)d_in[14];
    const float* ca_wo      = (const float*)d_in[15];
    const float* ca_bo      = (const float*)d_in[16];
    const float* gate_param = (const float*)d_in[17];
    const float* ffn_g      = (const float*)d_in[18];
    const float* ffn_b      = (const float*)d_in[19];
    const float* ffn_w1     = (const float*)d_in[20];
    const float* ffn_b1     = (const float*)d_in[21];
    const float* ffn_w2     = (const float*)d_in[22];
    const float* ffn_b2     = (const float*)d_in[23];
    float* out = (float*)d_out;

    float* S = nullptr;
    cudaGetSymbolAddress((void**)&S, g_scratch);
    float* ln   = S + OFF_LN;
    float* qkv  = S + OFF_QKV;
    float* attn = S + OFF_ATTN;
    float* x1   = S + OFF_X1;
    float* x2   = S + OFF_X2;
    float* kvn  = S + OFF_KVN;
    float* ckv  = S + OFF_CKV;
    float* f    = S + OFF_F;
    float* gg   = S + OFF_GG;

    // ---- Self-attention ----
    ln_kernel<<<M_, 256>>>(x, norm1_g, norm1_b, ln);
    gemm_kernel<0><<<dim3(3 * D_ / 128, M_ / 128), 256>>>(
        ln, sa_wqkv, sa_bqkv, nullptr, nullptr, qkv, M_, 3 * D_, D_);
    flash_kernel<<<dim3(L_ / 64, B_ * H_), 256>>>(
        qkv, 3 * D_, qkv + D_, 3 * D_, qkv + 2 * D_, 3 * D_,
        alibi, attn, D_, L_, L_);
    gemm_kernel<1><<<dim3(D_ / 128, M_ / 128), 256>>>(
        attn, sa_wo, sa_bo, x, nullptr, x1, M_, D_, D_);

    // ---- Cross-attention ----
    ln_kernel<<<M_, 256>>>(x1, ca_nq_g, ca_nq_b, ln);
    ln_kernel<<<B_ * NS_, 256>>>(species, ca_nkv_g, ca_nkv_b, kvn);
    gemm_kernel<0><<<dim3(D_ / 128, M_ / 128), 256>>>(
        ln, ca_wqkv, ca_bqkv, nullptr, nullptr, attn /* cq */, M_, D_, D_);
    gemm_kernel<0><<<dim3(2 * D_ / 128, (B_ * NS_) / 128), 256>>>(
        kvn, ca_wqkv + (size_t)D_ * D_, ca_bqkv + D_, nullptr, nullptr,
        ckv, B_ * NS_, 2 * D_, D_);
    flash_kernel<<<dim3(L_ / 64, B_ * H_), 256>>>(
        attn, D_, ckv, 2 * D_, ckv + D_, 2 * D_,
        nullptr, ln /* cross out */, D_, L_, NS_);
    gemm_kernel<2><<<dim3(D_ / 128, M_ / 128), 256>>>(
        ln, ca_wo, ca_bo, x1, gate_param, x2, M_, D_, D_);

    // ---- FFN (GEGLU) ----
    ln_kernel<<<M_, 256>>>(x2, ffn_g, ffn_b, attn);
    gemm_kernel<0><<<dim3(2 * FF_ / 128, M_ / 128), 256>>>(
        attn, ffn_w1, ffn_b1, nullptr, nullptr, f, M_, 2 * FF_, D_);
    geglu_kernel<<<(M_ * FF_ / 4) / 256, 256>>>(f, gg);
    gemm_kernel<1><<<dim3(D_ / 128, M_ / 128), 256>>>(
        gg, ffn_w2, ffn_b2, x2, nullptr, out, M_, D_, FF_);
}